// round 4
// baseline (speedup 1.0000x reference)
#include <cuda_runtime.h>
#include <math.h>

// Problem constants (match reference)
#define N_NODES 100000
#define E_EDGES 1600000
#define NF 128
#define NH 64
#define EPSV 1e-15f
#define MXN 0.996f          // (1 - 4e-3)/sqrt(c), c=1
#define CLIPV 0.9999999f    // 1 - 1e-7 artanh clip

// Scratch (no cudaMalloc allowed) ------------------------------------------
__device__ float d_h0[N_NODES * NF];    // proj(expmap0(x))
__device__ float d_ht[N_NODES * NH];    // tangent-space features per layer
__device__ float d_agg[N_NODES * NH];   // SpMM accumulator
__device__ float d_hb[3][NH];           // proj(expmap0(b_l))
__device__ float d_y2[3];               // ||hyp_b||^2 per layer

__device__ __forceinline__ float wredsum(float v) {
    #pragma unroll
    for (int o = 16; o; o >>= 1) v += __shfl_xor_sync(0xffffffffu, v, o);
    return v;
}

// HypAct gate: given u (row held as lane/lane+32 pair), returns f such that
// hypact(u) = relu(u) * f, and outputs m2 = ||hypact(u)|| and n2, st for reuse.
// hypact = proj(expmap0(relu(logmap0(proj(expmap0(u)))))) ; relu commutes with
// the positive scalings, so only ||u|| and ||relu(u)|| are needed.
__device__ __forceinline__ void hypact_gate(float u0, float u1,
                                            float& f, float& m2,
                                            float& n2, float& st) {
    float ss  = wredsum(u0 * u0 + u1 * u1);
    float ssp = wredsum((u0 > 0.f ? u0 * u0 : 0.f) + (u1 > 0.f ? u1 * u1 : 0.f));
    float n1 = fmaxf(sqrtf(ss), EPSV);
    float m1 = fminf(tanhf(n1), MXN);
    float s1 = m1 / n1;                                        // p = u*s1, ||p|| = m1
    float l = atanhf(fminf(fmaxf(m1, EPSV), CLIPV)) / fmaxf(m1, EPSV);
    st = s1 * l;                                                // t = u*st (st >= 0)
    n2 = fmaxf(st * sqrtf(ssp), EPSV);                          // ||relu(t)||
    m2 = fminf(tanhf(n2), MXN);
    f = st * (m2 / n2);
}

// ---------------------------------------------------------------------------
// h0 = proj(expmap0(x)), rows of width 128. One warp per row, float4 loads.
// Also zeroes d_agg ahead of the first SpMM (each warp zeroes its row).
__global__ void k_init(const float* __restrict__ x) {
    int row = blockIdx.x * (blockDim.x >> 5) + (threadIdx.x >> 5);
    if (row >= N_NODES) return;
    int lane = threadIdx.x & 31;
    float4 v = *(const float4*)&x[(size_t)row * NF + lane * 4];
    float ss = wredsum(v.x * v.x + v.y * v.y + v.z * v.z + v.w * v.w);
    float n = fmaxf(sqrtf(ss), EPSV);
    float s = fminf(tanhf(n), MXN) / n;   // expmap0 scale fused with proj clamp
    float4 o = make_float4(v.x * s, v.y * s, v.z * s, v.w * s);
    *(float4*)&d_h0[(size_t)row * NF + lane * 4] = o;
    if (lane < 16)
        ((float4*)&d_agg[(size_t)row * NH])[lane] = make_float4(0.f, 0.f, 0.f, 0.f);
}

// ---------------------------------------------------------------------------
// hyp_b = proj(expmap0(b)) and its squared norm, 3 layers, one warp each.
__global__ void k_bias(const float* __restrict__ b1, const float* __restrict__ b2,
                       const float* __restrict__ b3) {
    int w = threadIdx.x >> 5, lane = threadIdx.x & 31;
    if (w >= 3) return;
    const float* b = (w == 0) ? b1 : (w == 1) ? b2 : b3;
    float v0 = b[lane], v1 = b[lane + 32];
    float ss = wredsum(v0 * v0 + v1 * v1);
    float n = fmaxf(sqrtf(ss), EPSV);
    float s = fminf(tanhf(n), MXN) / n;
    float h0v = v0 * s, h1v = v1 * s;
    d_hb[w][lane] = h0v;
    d_hb[w][lane + 32] = h1v;
    float y2 = wredsum(h0v * h0v + h1v * h1v);
    if (lane == 0) d_y2[w] = y2;
}

// ---------------------------------------------------------------------------
// HypLinear (mobius_matvec + proj + mobius_add(bias) + proj) fused with
// logmap0 -> writes tangent features d_ht[N, 64].
// FUSE_ACT: input is d_agg (previous layer's SpMM result); HypAct is applied
// on the fly during staging and d_agg is re-zeroed for the next SpMM.
// NW warps/block, TILE rows/warp; lane owns output features lane & lane+32.
// W staged transposed with stride 65 (conflict-free both directions).
template <int DIN, int TILE, int NW, bool FUSE_ACT>
__global__ void k_hyplinear(const float* __restrict__ hin,
                            const float* __restrict__ W, int li) {
    __shared__ float Wt[DIN * (NH + 1)];                 // Wt[k*65 + j] = W[j, k]
    __shared__ float htile[NW * TILE * DIN];
    __shared__ float shb[NH];

    int tid = threadIdx.x, w = tid >> 5, lane = tid & 31;

    for (int i = tid; i < DIN * NH; i += blockDim.x) {
        int j = i / DIN, k = i - j * DIN;                // coalesced read of W
        Wt[k * (NH + 1) + j] = W[i];                     // padded write: no conflicts
    }
    if (tid < NH) shb[tid] = d_hb[li][tid];
    __syncthreads();

    float y2 = d_y2[li];
    int rowbase = blockIdx.x * (NW * TILE) + w * TILE;
    float* ht_ = &htile[w * TILE * DIN];

    // Stage h rows into smem; per-row ||p||^2 comes out of the staging pass.
    float pn2[TILE];
    #pragma unroll
    for (int t = 0; t < TILE; t++) {
        int r = rowbase + t;
        if (FUSE_ACT) {
            float v0 = 0.f, v1 = 0.f, m2 = 0.f;
            if (r < N_NODES) {                           // uniform across warp
                float u0 = d_agg[(size_t)r * NH + lane];
                float u1 = d_agg[(size_t)r * NH + lane + 32];
                d_agg[(size_t)r * NH + lane]      = 0.f; // re-zero for next SpMM
                d_agg[(size_t)r * NH + lane + 32] = 0.f;
                float f, n2, st;
                hypact_gate(u0, u1, f, m2, n2, st);
                v0 = (u0 > 0.f) ? u0 * f : 0.f;
                v1 = (u1 > 0.f) ? u1 * f : 0.f;
            }
            ht_[t * DIN + lane]      = v0;
            ht_[t * DIN + lane + 32] = v1;
            pn2[t] = m2 * m2;                            // ||hypact(u)|| = m2 exactly
        } else {
            float lss = 0.f;
            if (r < N_NODES) {
                for (int k = lane; k < DIN; k += 32) {
                    float v = __ldg(&hin[(size_t)r * DIN + k]);
                    ht_[t * DIN + k] = v;
                    lss += v * v;
                }
            } else {
                for (int k = lane; k < DIN; k += 32) ht_[t * DIN + k] = 0.f;
            }
            pn2[t] = wredsum(lss);
        }
    }
    __syncwarp();

    // Register-tiled GEMM: mp = p @ W^T.
    float acc0[TILE], acc1[TILE];
    #pragma unroll
    for (int t = 0; t < TILE; t++) { acc0[t] = 0.f; acc1[t] = 0.f; }
    for (int k = 0; k < DIN; k++) {
        float w0 = Wt[k * (NH + 1) + lane];
        float w1 = Wt[k * (NH + 1) + lane + 32];
        #pragma unroll
        for (int t = 0; t < TILE; t++) {
            float hk = ht_[t * DIN + k];                 // smem broadcast
            acc0[t] = fmaf(hk, w0, acc0[t]);
            acc1[t] = fmaf(hk, w1, acc1[t]);
        }
    }

    float hb0 = shb[lane], hb1 = shb[lane + 32];
    #pragma unroll
    for (int t = 0; t < TILE; t++) {
        int r = rowbase + t;
        if (r >= N_NODES) break;                         // uniform across warp
        // mobius_matvec tail
        float mpn2 = wredsum(acc0[t] * acc0[t] + acc1[t] * acc1[t]);
        float mpn = sqrtf(mpn2);
        float pn = fmaxf(sqrtf(pn2[t]), EPSV);
        float pnc = fminf(pn, CLIPV);
        float tn = tanhf(mpn / pn * atanhf(pnc));
        float m1 = fminf(tn, MXN);                        // proj fused: ||res|| = tanh
        float s = (mpn <= EPSV) ? 0.f : m1 / fmaxf(mpn, EPSV);
        float r0 = acc0[t] * s, r1 = acc1[t] * s;
        // mobius_add(res, hyp_b)
        float x2 = wredsum(r0 * r0 + r1 * r1);
        float xy = wredsum(r0 * hb0 + r1 * hb1);
        float A = 1.f + 2.f * xy + y2;
        float B = 1.f - x2;
        float den = fmaxf(1.f + 2.f * xy + x2 * y2, EPSV);
        float v0 = (A * r0 + B * hb0) / den;
        float v1 = (A * r1 + B * hb1) / den;
        // proj + logmap0
        float n3 = fmaxf(sqrtf(wredsum(v0 * v0 + v1 * v1)), EPSV);
        float sp = (n3 > MXN) ? (MXN / n3) : 1.f;
        float n3p = fminf(n3, MXN);
        float ls = atanhf(fminf(n3p, CLIPV)) / fmaxf(n3p, EPSV);
        float sc = sp * ls;
        d_ht[(size_t)r * NH + lane]      = v0 * sc;
        d_ht[(size_t)r * NH + lane + 32] = v1 * sc;
    }
}

// ---------------------------------------------------------------------------
// SpMM: agg[dst] += adj_val * ht[src].
// One warp serves 2 edges (16 lanes each, float4 per lane). Lanes 0/16 load
// the edge scalars once and shfl-broadcast (kills 16x redundant LDGs).
// Vectorized no-return reduction keeps L2 the only limiter.
__global__ void k_spmm(const int* __restrict__ src, const int* __restrict__ dst,
                       const float* __restrict__ av) {
    int warp = blockIdx.x * (blockDim.x >> 5) + (threadIdx.x >> 5);
    int lane = threadIdx.x & 31;
    int e = warp * 2 + (lane >> 4);
    if (e >= E_EDGES) return;
    int q = lane & 15;
    int s = 0, d = 0; float a = 0.f;
    if (q == 0) {                       // lanes 0 and 16 fetch edge scalars
        s = __ldg(&src[e]);
        d = __ldg(&dst[e]);
        a = __ldg(&av[e]);
    }
    int srcLane = lane & 16;            // broadcast within each 16-lane group
    s = __shfl_sync(0xffffffffu, s, srcLane);
    d = __shfl_sync(0xffffffffu, d, srcLane);
    a = __shfl_sync(0xffffffffu, a, srcLane);
    float4 v = __ldg((const float4*)&d_ht[(size_t)s * NH + q * 4]);
    float* o = &d_agg[(size_t)d * NH + q * 4];
    asm volatile("red.global.add.v4.f32 [%0], {%1, %2, %3, %4};"
                 :: "l"(o), "f"(v.x * a), "f"(v.y * a), "f"(v.z * a), "f"(v.w * a)
                 : "memory");
}

// ---------------------------------------------------------------------------
// Head, fused with the final HypAct:
//   t = logmap0(hypact(agg)) = relu(u) * st * atanh(m2)/n2
//   z = relu(t@W4^T+b4); out = log_softmax(z@W5^T+b5).
// 1024 threads (32 warps) to amortize the weight staging 4x.
__global__ void k_head(const float* __restrict__ W4, const float* __restrict__ b4,
                       const float* __restrict__ W5, const float* __restrict__ b5,
                       float* __restrict__ out) {
    __shared__ float sW4[64 * 33];   // sW4[k*33 + j] = W4[j, k]  (padded)
    __shared__ float sW5[32 * 17];   // sW5[k*17 + j] = W5[j, k]
    __shared__ float sb4[32], sb5[16];
    int tid = threadIdx.x;
    for (int i = tid; i < 32 * 64; i += blockDim.x) {
        int j = i / 64, k = i - j * 64;
        sW4[k * 33 + j] = W4[i];
    }
    for (int i = tid; i < 16 * 32; i += blockDim.x) {
        int j = i / 32, k = i - j * 32;
        sW5[k * 17 + j] = W5[i];
    }
    if (tid < 32) sb4[tid] = b4[tid];
    if (tid < 16) sb5[tid] = b5[tid];
    __syncthreads();

    int row = blockIdx.x * (blockDim.x >> 5) + (tid >> 5);
    if (row >= N_NODES) return;
    int lane = tid & 31;
    float u0 = d_agg[(size_t)row * NH + lane];
    float u1 = d_agg[(size_t)row * NH + lane + 32];
    float f, m2, n2, st;
    hypact_gate(u0, u1, f, m2, n2, st);
    // logmap0 of the hypact output: scale = st * atanh(m2)/n2
    float lt = st * atanhf(fminf(fmaxf(m2, EPSV), CLIPV)) / n2;
    float t0 = (u0 > 0.f) ? u0 * lt : 0.f;
    float t1 = (u1 > 0.f) ? u1 * lt : 0.f;

    float z = sb4[lane];
    #pragma unroll
    for (int k = 0; k < 32; k++) {
        float tk = __shfl_sync(0xffffffffu, t0, k);
        z = fmaf(tk, sW4[k * 33 + lane], z);
    }
    #pragma unroll
    for (int k = 0; k < 32; k++) {
        float tk = __shfl_sync(0xffffffffu, t1, k);
        z = fmaf(tk, sW4[(k + 32) * 33 + lane], z);
    }
    z = fmaxf(z, 0.f);

    float o = (lane < 16) ? sb5[lane] : -1e30f;
    #pragma unroll
    for (int k = 0; k < 32; k++) {
        float zk = __shfl_sync(0xffffffffu, z, k);
        if (lane < 16) o = fmaf(zk, sW5[k * 17 + lane], o);
    }
    // log_softmax over the 16 logits on lanes 0..15 (xor offsets <= 8 keep
    // lanes 0-15 and 16-31 in separate groups).
    float m = o;
    #pragma unroll
    for (int off = 8; off; off >>= 1) m = fmaxf(m, __shfl_xor_sync(0xffffffffu, m, off));
    float eo = expf(o - m);
    float ssum = eo;
    #pragma unroll
    for (int off = 8; off; off >>= 1) ssum += __shfl_xor_sync(0xffffffffu, ssum, off);
    if (lane < 16) out[(size_t)row * 16 + lane] = o - m - logf(ssum);
}

// ---------------------------------------------------------------------------
extern "C" void kernel_launch(void* const* d_in, const int* in_sizes, int n_in,
                              void* d_out, int out_size) {
    const float* x   = (const float*)d_in[0];
    const int*   src = (const int*)  d_in[1];
    const int*   dst = (const int*)  d_in[2];
    const float* av  = (const float*)d_in[3];
    const float* W1  = (const float*)d_in[4];
    const float* b1  = (const float*)d_in[5];
    const float* W2  = (const float*)d_in[6];
    const float* b2  = (const float*)d_in[7];
    const float* W3  = (const float*)d_in[8];
    const float* b3  = (const float*)d_in[9];
    const float* W4  = (const float*)d_in[10];
    const float* b4  = (const float*)d_in[11];
    const float* W5  = (const float*)d_in[12];
    const float* b5  = (const float*)d_in[13];
    float* out = (float*)d_out;

    const int WPB = 8;
    int rowBlocks = (N_NODES + WPB - 1) / WPB;

    k_bias<<<1, 96>>>(b1, b2, b3);
    k_init<<<rowBlocks, WPB * 32>>>(x);   // also zeroes d_agg

    // SpMM: 2 edges per warp, 8 warps per block => 16 edges/block.
    int spmmBlocks = (E_EDGES + 15) / 16;

    // Layer 1 (DIN=128): 4 warps x TILE 6 (static smem ~45.8KB)
    {
        int blocks = (N_NODES + 4 * 6 - 1) / (4 * 6);
        k_hyplinear<128, 6, 4, false><<<blocks, 128>>>(d_h0, W1, 0);
        k_spmm<<<spmmBlocks, 256>>>(src, dst, av);
    }
    // Layer 2 (DIN=64, HypAct fused into staging): 8 warps x TILE 8
    {
        int blocks = (N_NODES + 8 * 8 - 1) / (8 * 8);
        k_hyplinear<64, 8, 8, true><<<blocks, 256>>>(nullptr, W2, 1);
        k_spmm<<<spmmBlocks, 256>>>(src, dst, av);
    }
    // Layer 3 (DIN=64, HypAct fused)
    {
        int blocks = (N_NODES + 8 * 8 - 1) / (8 * 8);
        k_hyplinear<64, 8, 8, true><<<blocks, 256>>>(nullptr, W3, 2);
        k_spmm<<<spmmBlocks, 256>>>(src, dst, av);
    }

    // Head (final HypAct fused): 32 warps/block.
    int headBlocks = (N_NODES + 31) / 32;
    k_head<<<headBlocks, 1024>>>(W4, b4, W5, b5, out);
}

// round 7
// speedup vs baseline: 1.4335x; 1.4335x over previous
#include <cuda_runtime.h>
#include <math.h>

// Problem constants (match reference)
#define N_NODES 100000
#define E_EDGES 1600000
#define NF 128
#define NH 64
#define EPSV 1e-15f
#define MXN 0.996f          // (1 - 4e-3)/sqrt(c), c=1
#define CLIPV 0.9999999f    // 1 - 1e-7 artanh clip
#define CAP 80              // per-dst bucket capacity (Poisson(16) tail: safe)

// Scratch (no cudaMalloc allowed) ------------------------------------------
__device__ float d_h0[N_NODES * NF];    // proj(expmap0(x))
__device__ float d_ht[N_NODES * NH];    // tangent-space features per layer
__device__ float d_agg[N_NODES * NH];   // aggregation result
__device__ float d_hb[3][NH];           // proj(expmap0(b_l))
__device__ float d_y2[3];               // ||hyp_b||^2 per layer
__device__ int   d_cnt[N_NODES];        // per-dst edge counts
__device__ uint2 d_ent[(size_t)N_NODES * CAP];  // (src, adj_val) buckets

__device__ __forceinline__ float wredsum(float v) {
    #pragma unroll
    for (int o = 16; o; o >>= 1) v += __shfl_xor_sync(0xffffffffu, v, o);
    return v;
}

// HypAct gate: hypact(u) = relu(u) * f ; m2 = ||hypact(u)||, n2/st for reuse.
// relu commutes with the positive scalings, so only ||u||, ||relu(u)|| needed.
__device__ __forceinline__ void hypact_gate(float u0, float u1,
                                            float& f, float& m2,
                                            float& n2, float& st) {
    float ss  = wredsum(u0 * u0 + u1 * u1);
    float ssp = wredsum((u0 > 0.f ? u0 * u0 : 0.f) + (u1 > 0.f ? u1 * u1 : 0.f));
    float n1 = fmaxf(sqrtf(ss), EPSV);
    float m1 = fminf(tanhf(n1), MXN);
    float s1 = m1 / n1;                                        // ||p|| = m1
    float l = atanhf(fminf(fmaxf(m1, EPSV), CLIPV)) / fmaxf(m1, EPSV);
    st = s1 * l;                                                // t = u*st, st >= 0
    n2 = fmaxf(st * sqrtf(ssp), EPSV);                          // ||relu(t)||
    m2 = fminf(tanhf(n2), MXN);
    f = st * (m2 / n2);
}

// ---------------------------------------------------------------------------
// h0 = proj(expmap0(x)), one warp per row, float4 loads. Also zeroes d_cnt
// every call so the bucket build is deterministic under graph replay.
__global__ void k_init(const float* __restrict__ x) {
    int gtid = blockIdx.x * blockDim.x + threadIdx.x;
    if (gtid < N_NODES) d_cnt[gtid] = 0;
    int row = gtid >> 5;
    if (row >= N_NODES) return;
    int lane = threadIdx.x & 31;
    float4 v = __ldg((const float4*)&x[(size_t)row * NF + lane * 4]);
    float ss = wredsum(v.x * v.x + v.y * v.y + v.z * v.z + v.w * v.w);
    float n = fmaxf(sqrtf(ss), EPSV);
    float s = fminf(tanhf(n), MXN) / n;   // expmap0 scale fused with proj clamp
    float4 o = make_float4(v.x * s, v.y * s, v.z * s, v.w * s);
    *(float4*)&d_h0[(size_t)row * NF + lane * 4] = o;
}

// ---------------------------------------------------------------------------
// Bucketed-CSR build: scatter (src, adj) into per-dst buckets. Once per call.
__global__ void k_build(const int* __restrict__ src, const int* __restrict__ dst,
                        const float* __restrict__ av) {
    int e = blockIdx.x * blockDim.x + threadIdx.x;
    if (e >= E_EDGES) return;
    int d = __ldg(&dst[e]);
    int pos = atomicAdd(&d_cnt[d], 1);
    if (pos < CAP)
        d_ent[(size_t)d * CAP + pos] =
            make_uint2((unsigned)__ldg(&src[e]), __float_as_uint(__ldg(&av[e])));
}

// ---------------------------------------------------------------------------
// Aggregation, no atomics: one warp per dst row. Two 16-lane halves process
// alternating edges; each lane owns a float4 column slice; halves combined by
// shfl_xor 16. Software-pipelined by one entry so the entry->gather dependent
// chain overlaps across iterations (raises per-warp MLP to ~2 chains).
// Writes ALL rows (zeros for deg 0) -> d_agg needs no pre-zero.
__global__ void k_agg() {
    int dstRow = blockIdx.x * (blockDim.x >> 5) + (threadIdx.x >> 5);
    if (dstRow >= N_NODES) return;
    int lane = threadIdx.x & 31;
    int half = lane >> 4, q = lane & 15;
    int deg = d_cnt[dstRow];
    if (deg > CAP) deg = CAP;
    const uint2* base = &d_ent[(size_t)dstRow * CAP];
    float4 acc = make_float4(0.f, 0.f, 0.f, 0.f);

    int i = half;
    uint2 en_next = (i < deg) ? __ldg(&base[i]) : make_uint2(0u, 0u);
    while (i < deg) {
        uint2 en = en_next;
        int inext = i + 2;
        if (inext < deg) en_next = __ldg(&base[inext]);   // prefetch next entry
        float a = __uint_as_float(en.y);
        float4 v = __ldg((const float4*)&d_ht[(size_t)en.x * NH + q * 4]);
        acc.x = fmaf(a, v.x, acc.x);
        acc.y = fmaf(a, v.y, acc.y);
        acc.z = fmaf(a, v.z, acc.z);
        acc.w = fmaf(a, v.w, acc.w);
        i = inext;
    }
    acc.x += __shfl_xor_sync(0xffffffffu, acc.x, 16);
    acc.y += __shfl_xor_sync(0xffffffffu, acc.y, 16);
    acc.z += __shfl_xor_sync(0xffffffffu, acc.z, 16);
    acc.w += __shfl_xor_sync(0xffffffffu, acc.w, 16);
    if (lane < 16)
        *(float4*)&d_agg[(size_t)dstRow * NH + lane * 4] = acc;
}

// ---------------------------------------------------------------------------
// hyp_b = proj(expmap0(b)) and its squared norm, 3 layers, one warp each.
__global__ void k_bias(const float* __restrict__ b1, const float* __restrict__ b2,
                       const float* __restrict__ b3) {
    int w = threadIdx.x >> 5, lane = threadIdx.x & 31;
    if (w >= 3) return;
    const float* b = (w == 0) ? b1 : (w == 1) ? b2 : b3;
    float v0 = b[lane], v1 = b[lane + 32];
    float ss = wredsum(v0 * v0 + v1 * v1);
    float n = fmaxf(sqrtf(ss), EPSV);
    float s = fminf(tanhf(n), MXN) / n;
    float h0v = v0 * s, h1v = v1 * s;
    d_hb[w][lane] = h0v;
    d_hb[w][lane + 32] = h1v;
    float y2 = wredsum(h0v * h0v + h1v * h1v);
    if (lane == 0) d_y2[w] = y2;
}

// ---------------------------------------------------------------------------
// HypLinear (mobius_matvec + proj + mobius_add(bias) + proj) fused with
// logmap0 -> d_ht[N, 64]. FUSE_ACT: input is d_agg; HypAct applied on the fly
// during staging (and ||hypact(u)|| = m2 exactly, so pn2 is free).
// Wt stride DIN+4 floats: lane phase pattern (4i mod 32) covers all banks ->
// LDS.128 conflict-free; ht reads are float4 broadcasts.
template <int DIN, int TILE, int NW, bool FUSE_ACT>
__global__ void k_hyplinear(const float* __restrict__ hin,
                            const float* __restrict__ W, int li) {
    __shared__ __align__(16) float Wt[NH * (DIN + 4)];   // Wt[j][k], stride DIN+4
    __shared__ __align__(16) float htile[NW * TILE * DIN];
    __shared__ float shb[NH];

    int tid = threadIdx.x, w = tid >> 5, lane = tid & 31;

    // Stage W with float4 loads (W is [NH][DIN] row-major, DIN mult of 4).
    for (int i4 = tid; i4 < NH * DIN / 4; i4 += blockDim.x) {
        int j = i4 / (DIN / 4), kq = i4 - j * (DIN / 4);
        float4 wv = __ldg(&((const float4*)W)[i4]);
        *(float4*)&Wt[j * (DIN + 4) + kq * 4] = wv;
    }
    if (tid < NH) shb[tid] = d_hb[li][tid];
    __syncthreads();

    float y2 = d_y2[li];
    int rowbase = blockIdx.x * (NW * TILE) + w * TILE;
    float* ht_ = &htile[w * TILE * DIN];

    // Stage rows into smem; per-row ||p||^2 falls out of the staging pass.
    float pn2[TILE];
    #pragma unroll
    for (int t = 0; t < TILE; t++) {
        int r = rowbase + t;
        if (FUSE_ACT) {
            float v0 = 0.f, v1 = 0.f, m2 = 0.f;
            if (r < N_NODES) {                           // uniform across warp
                float u0 = d_agg[(size_t)r * NH + lane];
                float u1 = d_agg[(size_t)r * NH + lane + 32];
                float f, n2, st;
                hypact_gate(u0, u1, f, m2, n2, st);
                v0 = (u0 > 0.f) ? u0 * f : 0.f;
                v1 = (u1 > 0.f) ? u1 * f : 0.f;
            }
            ht_[t * DIN + lane]      = v0;
            ht_[t * DIN + lane + 32] = v1;
            pn2[t] = m2 * m2;                            // exact ||hypact(u)||^2
        } else {
            // DIN == 128: one float4 per lane covers the row.
            float4 v = make_float4(0.f, 0.f, 0.f, 0.f);
            if (r < N_NODES)
                v = __ldg((const float4*)&hin[(size_t)r * DIN + lane * 4]);
            *(float4*)&ht_[t * DIN + lane * 4] = v;
            pn2[t] = wredsum(v.x * v.x + v.y * v.y + v.z * v.z + v.w * v.w);
        }
    }
    __syncwarp();

    // Register-tiled GEMM: mp = p @ W^T, float4 k-chunks.
    float acc0[TILE], acc1[TILE];
    #pragma unroll
    for (int t = 0; t < TILE; t++) { acc0[t] = 0.f; acc1[t] = 0.f; }
    #pragma unroll 4
    for (int k4 = 0; k4 < DIN / 4; k4++) {
        float4 w0 = *(float4*)&Wt[lane * (DIN + 4) + k4 * 4];
        float4 w1 = *(float4*)&Wt[(lane + 32) * (DIN + 4) + k4 * 4];
        #pragma unroll
        for (int t = 0; t < TILE; t++) {
            float4 h = *(float4*)&ht_[t * DIN + k4 * 4];  // smem broadcast
            acc0[t] = fmaf(h.x, w0.x, acc0[t]);
            acc0[t] = fmaf(h.y, w0.y, acc0[t]);
            acc0[t] = fmaf(h.z, w0.z, acc0[t]);
            acc0[t] = fmaf(h.w, w0.w, acc0[t]);
            acc1[t] = fmaf(h.x, w1.x, acc1[t]);
            acc1[t] = fmaf(h.y, w1.y, acc1[t]);
            acc1[t] = fmaf(h.z, w1.z, acc1[t]);
            acc1[t] = fmaf(h.w, w1.w, acc1[t]);
        }
    }

    float hb0 = shb[lane], hb1 = shb[lane + 32];
    #pragma unroll
    for (int t = 0; t < TILE; t++) {
        int r = rowbase + t;
        if (r >= N_NODES) break;                         // uniform across warp
        // mobius_matvec tail
        float mpn2 = wredsum(acc0[t] * acc0[t] + acc1[t] * acc1[t]);
        float mpn = sqrtf(mpn2);
        float pn = fmaxf(sqrtf(pn2[t]), EPSV);
        float pnc = fminf(pn, CLIPV);
        float tn = tanhf(mpn / pn * atanhf(pnc));
        float m1 = fminf(tn, MXN);                        // proj fused
        float s = (mpn <= EPSV) ? 0.f : m1 / fmaxf(mpn, EPSV);
        float r0 = acc0[t] * s, r1 = acc1[t] * s;
        // mobius_add(res, hyp_b)
        float x2 = wredsum(r0 * r0 + r1 * r1);
        float xy = wredsum(r0 * hb0 + r1 * hb1);
        float A = 1.f + 2.f * xy + y2;
        float B = 1.f - x2;
        float den = fmaxf(1.f + 2.f * xy + x2 * y2, EPSV);
        float v0 = (A * r0 + B * hb0) / den;
        float v1 = (A * r1 + B * hb1) / den;
        // proj + logmap0
        float n3 = fmaxf(sqrtf(wredsum(v0 * v0 + v1 * v1)), EPSV);
        float sp = (n3 > MXN) ? (MXN / n3) : 1.f;
        float n3p = fminf(n3, MXN);
        float ls = atanhf(fminf(n3p, CLIPV)) / fmaxf(n3p, EPSV);
        float sc = sp * ls;
        d_ht[(size_t)r * NH + lane]      = v0 * sc;
        d_ht[(size_t)r * NH + lane + 32] = v1 * sc;
    }
}

// ---------------------------------------------------------------------------
// Head, fused with the final HypAct:
//   t = logmap0(hypact(agg)) = relu(u) * st * atanh(m2)/n2
//   z = relu(t@W4^T+b4); out = log_softmax(z@W5^T+b5).
__global__ void k_head(const float* __restrict__ W4, const float* __restrict__ b4,
                       const float* __restrict__ W5, const float* __restrict__ b5,
                       float* __restrict__ out) {
    __shared__ float sW4[64 * 33];   // sW4[k*33 + j] = W4[j, k]  (padded)
    __shared__ float sW5[32 * 17];   // sW5[k*17 + j] = W5[j, k]
    __shared__ float sb4[32], sb5[16];
    int tid = threadIdx.x;
    for (int i = tid; i < 32 * 64; i += blockDim.x) {
        int j = i / 64, k = i - j * 64;
        sW4[k * 33 + j] = W4[i];
    }
    for (int i = tid; i < 16 * 32; i += blockDim.x) {
        int j = i / 32, k = i - j * 32;
        sW5[k * 17 + j] = W5[i];
    }
    if (tid < 32) sb4[tid] = b4[tid];
    if (tid < 16) sb5[tid] = b5[tid];
    __syncthreads();

    int row = blockIdx.x * (blockDim.x >> 5) + (tid >> 5);
    if (row >= N_NODES) return;
    int lane = tid & 31;
    float u0 = d_agg[(size_t)row * NH + lane];
    float u1 = d_agg[(size_t)row * NH + lane + 32];
    float f, m2, n2, st;
    hypact_gate(u0, u1, f, m2, n2, st);
    float lt = st * atanhf(fminf(fmaxf(m2, EPSV), CLIPV)) / n2;
    float t0 = (u0 > 0.f) ? u0 * lt : 0.f;
    float t1 = (u1 > 0.f) ? u1 * lt : 0.f;

    float z = sb4[lane];
    #pragma unroll
    for (int k = 0; k < 32; k++) {
        float tk = __shfl_sync(0xffffffffu, t0, k);
        z = fmaf(tk, sW4[k * 33 + lane], z);
    }
    #pragma unroll
    for (int k = 0; k < 32; k++) {
        float tk = __shfl_sync(0xffffffffu, t1, k);
        z = fmaf(tk, sW4[(k + 32) * 33 + lane], z);
    }
    z = fmaxf(z, 0.f);

    float o = (lane < 16) ? sb5[lane] : -1e30f;
    #pragma unroll
    for (int k = 0; k < 32; k++) {
        float zk = __shfl_sync(0xffffffffu, z, k);
        if (lane < 16) o = fmaf(zk, sW5[k * 17 + lane], o);
    }
    // log_softmax over 16 logits on lanes 0..15 (xor offsets <= 8 stay in-group)
    float m = o;
    #pragma unroll
    for (int off = 8; off; off >>= 1) m = fmaxf(m, __shfl_xor_sync(0xffffffffu, m, off));
    float eo = expf(o - m);
    float ssum = eo;
    #pragma unroll
    for (int off = 8; off; off >>= 1) ssum += __shfl_xor_sync(0xffffffffu, ssum, off);
    if (lane < 16) out[(size_t)row * 16 + lane] = o - m - logf(ssum);
}

// ---------------------------------------------------------------------------
extern "C" void kernel_launch(void* const* d_in, const int* in_sizes, int n_in,
                              void* d_out, int out_size) {
    const float* x   = (const float*)d_in[0];
    const int*   src = (const int*)  d_in[1];
    const int*   dst = (const int*)  d_in[2];
    const float* av  = (const float*)d_in[3];
    const float* W1  = (const float*)d_in[4];
    const float* b1  = (const float*)d_in[5];
    const float* W2  = (const float*)d_in[6];
    const float* b2  = (const float*)d_in[7];
    const float* W3  = (const float*)d_in[8];
    const float* b3  = (const float*)d_in[9];
    const float* W4  = (const float*)d_in[10];
    const float* b4  = (const float*)d_in[11];
    const float* W5  = (const float*)d_in[12];
    const float* b5  = (const float*)d_in[13];
    float* out = (float*)d_out;

    int rowBlocks = (N_NODES + 7) / 8;          // 8 warps/block row kernels

    k_bias<<<1, 96>>>(b1, b2, b3);
    k_init<<<rowBlocks, 256>>>(x);              // also zeroes d_cnt
    k_build<<<(E_EDGES + 255) / 256, 256>>>(src, dst, av);

    // Layer 1 (DIN=128): 4 warps x TILE 6 (smem ~46KB)
    {
        int blocks = (N_NODES + 4 * 6 - 1) / (4 * 6);
        k_hyplinear<128, 6, 4, false><<<blocks, 128>>>(d_h0, W1, 0);
        k_agg<<<rowBlocks, 256>>>();
    }
    // Layer 2 (DIN=64, HypAct fused into staging): 8 warps x TILE 8
    {
        int blocks = (N_NODES + 8 * 8 - 1) / (8 * 8);
        k_hyplinear<64, 8, 8, true><<<blocks, 256>>>(nullptr, W2, 1);
        k_agg<<<rowBlocks, 256>>>();
    }
    // Layer 3 (DIN=64, HypAct fused)
    {
        int blocks = (N_NODES + 8 * 8 - 1) / (8 * 8);
        k_hyplinear<64, 8, 8, true><<<blocks, 256>>>(nullptr, W3, 2);
        k_agg<<<rowBlocks, 256>>>();
    }

    // Head (final HypAct fused): 32 warps/block.
    int headBlocks = (N_NODES + 31) / 32;
    k_head<<<headBlocks, 1024>>>(W4, b4, W5, b5, out);
}

// round 14
// speedup vs baseline: 1.4828x; 1.0344x over previous
#include <cuda_runtime.h>
#include <math.h>

// Problem constants (match reference)
#define N_NODES 100000
#define E_EDGES 1600000
#define NF 128
#define NH 64
#define EPSV 1e-15f
#define MXN 0.996f          // (1 - 4e-3)/sqrt(c), c=1
#define CLIPV 0.9999999f    // 1 - 1e-7 artanh clip
#define CAP 80              // per-dst bucket capacity (Poisson(16) tail: safe)
#define HL_TILE 5
#define HL_NW 8

// Scratch (no cudaMalloc allowed) ------------------------------------------
__device__ float d_h0[N_NODES * NF];    // proj(expmap0(x))
__device__ float d_ht[N_NODES * NH];    // tangent-space features per layer
__device__ float d_agg[N_NODES * NH];   // aggregation result
__device__ float d_hb[3][NH];           // proj(expmap0(b_l))
__device__ float d_y2[3];               // ||hyp_b||^2 per layer
__device__ int   d_cnt[N_NODES];        // per-dst edge counts
__device__ uint2 d_ent[(size_t)N_NODES * CAP];  // (src, adj_val) buckets

__device__ __forceinline__ float wredsum(float v) {
    #pragma unroll
    for (int o = 16; o; o >>= 1) v += __shfl_xor_sync(0xffffffffu, v, o);
    return v;
}

// ---------------------------------------------------------------------------
// h0 = proj(expmap0(x)), one warp per row, float4 loads. Also zeroes d_cnt.
__global__ void k_init(const float* __restrict__ x) {
    int gtid = blockIdx.x * blockDim.x + threadIdx.x;
    if (gtid < N_NODES) d_cnt[gtid] = 0;
    int row = gtid >> 5;
    if (row >= N_NODES) return;
    int lane = threadIdx.x & 31;
    float4 v = __ldg((const float4*)&x[(size_t)row * NF + lane * 4]);
    float ss = wredsum(v.x * v.x + v.y * v.y + v.z * v.z + v.w * v.w);
    float n = fmaxf(sqrtf(ss), EPSV);
    float s = fminf(tanhf(n), MXN) / n;
    float4 o = make_float4(v.x * s, v.y * s, v.z * s, v.w * s);
    *(float4*)&d_h0[(size_t)row * NF + lane * 4] = o;
}

// ---------------------------------------------------------------------------
// Bucketed-CSR build: scatter (src, adj) into per-dst buckets. Once per call.
__global__ void k_build(const int* __restrict__ src, const int* __restrict__ dst,
                        const float* __restrict__ av) {
    int e = blockIdx.x * blockDim.x + threadIdx.x;
    if (e >= E_EDGES) return;
    int d = __ldg(&dst[e]);
    int pos = atomicAdd(&d_cnt[d], 1);
    if (pos < CAP)
        d_ent[(size_t)d * CAP + pos] =
            make_uint2((unsigned)__ldg(&src[e]), __float_as_uint(__ldg(&av[e])));
}

// ---------------------------------------------------------------------------
// Aggregation, no atomics: one warp per dst row; two 16-lane halves process
// alternating edges; software-pipelined entry prefetch; halves combined via
// shfl_xor 16. Writes ALL rows (zeros for deg 0) -> no pre-zero needed.
__global__ void k_agg() {
    int dstRow = blockIdx.x * (blockDim.x >> 5) + (threadIdx.x >> 5);
    if (dstRow >= N_NODES) return;
    int lane = threadIdx.x & 31;
    int half = lane >> 4, q = lane & 15;
    int deg = d_cnt[dstRow];
    if (deg > CAP) deg = CAP;
    const uint2* base = &d_ent[(size_t)dstRow * CAP];
    float4 acc = make_float4(0.f, 0.f, 0.f, 0.f);

    int i = half;
    uint2 en_next = (i < deg) ? __ldg(&base[i]) : make_uint2(0u, 0u);
    while (i < deg) {
        uint2 en = en_next;
        int inext = i + 2;
        if (inext < deg) en_next = __ldg(&base[inext]);   // prefetch next entry
        float a = __uint_as_float(en.y);
        float4 v = __ldg((const float4*)&d_ht[(size_t)en.x * NH + q * 4]);
        acc.x = fmaf(a, v.x, acc.x);
        acc.y = fmaf(a, v.y, acc.y);
        acc.z = fmaf(a, v.z, acc.z);
        acc.w = fmaf(a, v.w, acc.w);
        i = inext;
    }
    acc.x += __shfl_xor_sync(0xffffffffu, acc.x, 16);
    acc.y += __shfl_xor_sync(0xffffffffu, acc.y, 16);
    acc.z += __shfl_xor_sync(0xffffffffu, acc.z, 16);
    acc.w += __shfl_xor_sync(0xffffffffu, acc.w, 16);
    if (lane < 16)
        *(float4*)&d_agg[(size_t)dstRow * NH + lane * 4] = acc;
}

// ---------------------------------------------------------------------------
// hyp_b = proj(expmap0(b)) and its squared norm, 3 layers, one warp each.
__global__ void k_bias(const float* __restrict__ b1, const float* __restrict__ b2,
                       const float* __restrict__ b3) {
    int w = threadIdx.x >> 5, lane = threadIdx.x & 31;
    if (w >= 3) return;
    const float* b = (w == 0) ? b1 : (w == 1) ? b2 : b3;
    float v0 = b[lane], v1 = b[lane + 32];
    float ss = wredsum(v0 * v0 + v1 * v1);
    float n = fmaxf(sqrtf(ss), EPSV);
    float s = fminf(tanhf(n), MXN) / n;
    float h0v = v0 * s, h1v = v1 * s;
    d_hb[w][lane] = h0v;
    d_hb[w][lane + 32] = h1v;
    float y2 = wredsum(h0v * h0v + h1v * h1v);
    if (lane == 0) d_y2[w] = y2;
}

// ---------------------------------------------------------------------------
// HypLinear fused with logmap0 (and HypAct on input when FUSE_ACT).
// Latency-focused rewrite vs measured occ=22%/issue=22% profile:
//  - dynamic smem, NW=8 warps share Wt, launch_bounds(256,4) => 32 warps/SM
//  - epilogue phase-batched across TILE rows so reduction chains pipeline
//  - x2 = s^2 * mpn2 identity removes one reduction round entirely
template <int DIN, int TILE, int NW, bool FUSE_ACT>
__global__ void __launch_bounds__(NW * 32, 4)
k_hyplinear(const float* __restrict__ hin, const float* __restrict__ W, int li) {
    extern __shared__ float sdyn[];
    float* Wt    = sdyn;                          // [NH][DIN+4]
    float* htile = sdyn + NH * (DIN + 4);         // [NW*TILE][DIN]
    float* shb   = htile + NW * TILE * DIN;       // [NH]

    int tid = threadIdx.x, w = tid >> 5, lane = tid & 31;

    // Stage W with float4 loads (W is [NH][DIN] row-major, DIN mult of 4).
    for (int i4 = tid; i4 < NH * DIN / 4; i4 += blockDim.x) {
        int j = i4 / (DIN / 4), kq = i4 - j * (DIN / 4);
        float4 wv = __ldg(&((const float4*)W)[i4]);
        *(float4*)&Wt[j * (DIN + 4) + kq * 4] = wv;
    }
    if (tid < NH) shb[tid] = d_hb[li][tid];
    __syncthreads();

    float y2 = d_y2[li];
    int rowbase = blockIdx.x * (NW * TILE) + w * TILE;
    int nv = N_NODES - rowbase;            // valid rows this warp (warp-uniform)
    if (nv > TILE) nv = TILE;
    float* ht_ = &htile[w * TILE * DIN];

    // ---- Staging (batched loads, then pipelined reductions) ----
    float pn2[TILE];
    if (FUSE_ACT) {
        float u0[TILE], u1[TILE];
        #pragma unroll
        for (int t = 0; t < TILE; t++) {
            u0[t] = 0.f; u1[t] = 0.f;
            if (t < nv) {
                int r = rowbase + t;
                u0[t] = __ldg(&d_agg[(size_t)r * NH + lane]);
                u1[t] = __ldg(&d_agg[(size_t)r * NH + lane + 32]);
            }
        }
        float ssA[TILE], ssP[TILE];
        #pragma unroll
        for (int t = 0; t < TILE; t++) {
            ssA[t] = wredsum(u0[t] * u0[t] + u1[t] * u1[t]);
            ssP[t] = wredsum((u0[t] > 0.f ? u0[t] * u0[t] : 0.f) +
                             (u1[t] > 0.f ? u1[t] * u1[t] : 0.f));
        }
        #pragma unroll
        for (int t = 0; t < TILE; t++) {
            // hypact(u) = relu(u)*f ; ||hypact|| = m2 exactly
            float n1 = fmaxf(sqrtf(ssA[t]), EPSV);
            float m1 = fminf(tanhf(n1), MXN);
            float s1 = m1 / n1;
            float l = atanhf(fminf(fmaxf(m1, EPSV), CLIPV)) / fmaxf(m1, EPSV);
            float st = s1 * l;
            float n2 = fmaxf(st * sqrtf(ssP[t]), EPSV);
            float m2 = fminf(tanhf(n2), MXN);
            float f = st * (m2 / n2);
            float v0 = (u0[t] > 0.f) ? u0[t] * f : 0.f;
            float v1 = (u1[t] > 0.f) ? u1[t] * f : 0.f;
            ht_[t * DIN + lane]      = v0;
            ht_[t * DIN + lane + 32] = v1;
            pn2[t] = m2 * m2;
        }
    } else {
        // DIN == 128: one float4 per lane covers the row.
        float4 hv[TILE];
        #pragma unroll
        for (int t = 0; t < TILE; t++) {
            hv[t] = make_float4(0.f, 0.f, 0.f, 0.f);
            if (t < nv)
                hv[t] = __ldg((const float4*)&hin[(size_t)(rowbase + t) * DIN + lane * 4]);
        }
        #pragma unroll
        for (int t = 0; t < TILE; t++) {
            *(float4*)&ht_[t * DIN + lane * 4] = hv[t];
            pn2[t] = wredsum(hv[t].x * hv[t].x + hv[t].y * hv[t].y +
                             hv[t].z * hv[t].z + hv[t].w * hv[t].w);
        }
    }
    __syncwarp();

    // ---- Register-tiled GEMM: mp = p @ W^T, float4 k-chunks ----
    float acc0[TILE], acc1[TILE];
    #pragma unroll
    for (int t = 0; t < TILE; t++) { acc0[t] = 0.f; acc1[t] = 0.f; }
    #pragma unroll 4
    for (int k4 = 0; k4 < DIN / 4; k4++) {
        float4 w0 = *(float4*)&Wt[lane * (DIN + 4) + k4 * 4];
        float4 w1 = *(float4*)&Wt[(lane + 32) * (DIN + 4) + k4 * 4];
        #pragma unroll
        for (int t = 0; t < TILE; t++) {
            float4 h = *(float4*)&ht_[t * DIN + k4 * 4];  // smem broadcast
            acc0[t] = fmaf(h.x, w0.x, acc0[t]);
            acc0[t] = fmaf(h.y, w0.y, acc0[t]);
            acc0[t] = fmaf(h.z, w0.z, acc0[t]);
            acc0[t] = fmaf(h.w, w0.w, acc0[t]);
            acc1[t] = fmaf(h.x, w1.x, acc1[t]);
            acc1[t] = fmaf(h.y, w1.y, acc1[t]);
            acc1[t] = fmaf(h.z, w1.z, acc1[t]);
            acc1[t] = fmaf(h.w, w1.w, acc1[t]);
        }
    }

    // ---- Epilogue, phase-batched so reduction chains overlap across t ----
    float hb0 = shb[lane], hb1 = shb[lane + 32];
    float mpn2[TILE], sv[TILE];
    #pragma unroll
    for (int t = 0; t < TILE; t++)
        mpn2[t] = wredsum(acc0[t] * acc0[t] + acc1[t] * acc1[t]);
    #pragma unroll
    for (int t = 0; t < TILE; t++) {
        float mpn = sqrtf(mpn2[t]);
        float pn = fmaxf(sqrtf(pn2[t]), EPSV);
        float pnc = fminf(pn, CLIPV);
        float tn = tanhf(mpn / pn * atanhf(pnc));
        float m1 = fminf(tn, MXN);                 // proj fused: ||res|| = m1
        sv[t] = (mpn <= EPSV) ? 0.f : m1 / fmaxf(mpn, EPSV);
        acc0[t] *= sv[t];                          // acc becomes res
        acc1[t] *= sv[t];
    }
    float xy[TILE];
    #pragma unroll
    for (int t = 0; t < TILE; t++)
        xy[t] = wredsum(acc0[t] * hb0 + acc1[t] * hb1);
    #pragma unroll
    for (int t = 0; t < TILE; t++) {
        float x2 = sv[t] * sv[t] * mpn2[t];        // ||res||^2 (exact identity)
        float A = 1.f + 2.f * xy[t] + y2;
        float B = 1.f - x2;
        float den = fmaxf(1.f + 2.f * xy[t] + x2 * y2, EPSV);
        acc0[t] = (A * acc0[t] + B * hb0) / den;   // acc becomes v
        acc1[t] = (A * acc1[t] + B * hb1) / den;
    }
    float n32[TILE];
    #pragma unroll
    for (int t = 0; t < TILE; t++)
        n32[t] = wredsum(acc0[t] * acc0[t] + acc1[t] * acc1[t]);
    #pragma unroll
    for (int t = 0; t < TILE; t++) {
        if (t >= nv) break;                        // warp-uniform
        float n3 = fmaxf(sqrtf(n32[t]), EPSV);
        float sp = (n3 > MXN) ? (MXN / n3) : 1.f;  // proj
        float n3p = fminf(n3, MXN);
        float ls = atanhf(fminf(n3p, CLIPV)) / fmaxf(n3p, EPSV);
        float sc = sp * ls;                        // logmap0 scale
        int r = rowbase + t;
        d_ht[(size_t)r * NH + lane]      = acc0[t] * sc;
        d_ht[(size_t)r * NH + lane + 32] = acc1[t] * sc;
    }
}

// ---------------------------------------------------------------------------
// Head, fused with the final HypAct:
//   t = logmap0(hypact(agg)) = relu(u) * st * atanh(m2)/n2
//   z = relu(t@W4^T+b4); out = log_softmax(z@W5^T+b5).
__global__ void k_head(const float* __restrict__ W4, const float* __restrict__ b4,
                       const float* __restrict__ W5, const float* __restrict__ b5,
                       float* __restrict__ out) {
    __shared__ float sW4[64 * 33];   // sW4[k*33 + j] = W4[j, k]  (padded)
    __shared__ float sW5[32 * 17];   // sW5[k*17 + j] = W5[j, k]
    __shared__ float sb4[32], sb5[16];
    int tid = threadIdx.x;
    for (int i = tid; i < 32 * 64; i += blockDim.x) {
        int j = i / 64, k = i - j * 64;
        sW4[k * 33 + j] = W4[i];
    }
    for (int i = tid; i < 16 * 32; i += blockDim.x) {
        int j = i / 32, k = i - j * 32;
        sW5[k * 17 + j] = W5[i];
    }
    if (tid < 32) sb4[tid] = b4[tid];
    if (tid < 16) sb5[tid] = b5[tid];
    __syncthreads();

    int row = blockIdx.x * (blockDim.x >> 5) + (tid >> 5);
    if (row >= N_NODES) return;
    int lane = tid & 31;
    float u0 = d_agg[(size_t)row * NH + lane];
    float u1 = d_agg[(size_t)row * NH + lane + 32];
    float ss  = wredsum(u0 * u0 + u1 * u1);
    float ssp = wredsum((u0 > 0.f ? u0 * u0 : 0.f) + (u1 > 0.f ? u1 * u1 : 0.f));
    float n1 = fmaxf(sqrtf(ss), EPSV);
    float m1 = fminf(tanhf(n1), MXN);
    float s1 = m1 / n1;
    float l = atanhf(fminf(fmaxf(m1, EPSV), CLIPV)) / fmaxf(m1, EPSV);
    float st = s1 * l;
    float n2 = fmaxf(st * sqrtf(ssp), EPSV);
    float m2 = fminf(tanhf(n2), MXN);
    float lt = st * atanhf(fminf(fmaxf(m2, EPSV), CLIPV)) / n2;
    float t0 = (u0 > 0.f) ? u0 * lt : 0.f;
    float t1 = (u1 > 0.f) ? u1 * lt : 0.f;

    float z = sb4[lane];
    #pragma unroll
    for (int k = 0; k < 32; k++) {
        float tk = __shfl_sync(0xffffffffu, t0, k);
        z = fmaf(tk, sW4[k * 33 + lane], z);
    }
    #pragma unroll
    for (int k = 0; k < 32; k++) {
        float tk = __shfl_sync(0xffffffffu, t1, k);
        z = fmaf(tk, sW4[(k + 32) * 33 + lane], z);
    }
    z = fmaxf(z, 0.f);

    float o = (lane < 16) ? sb5[lane] : -1e30f;
    #pragma unroll
    for (int k = 0; k < 32; k++) {
        float zk = __shfl_sync(0xffffffffu, z, k);
        if (lane < 16) o = fmaf(zk, sW5[k * 17 + lane], o);
    }
    float m = o;
    #pragma unroll
    for (int off = 8; off; off >>= 1) m = fmaxf(m, __shfl_xor_sync(0xffffffffu, m, off));
    float eo = expf(o - m);
    float ssum = eo;
    #pragma unroll
    for (int off = 8; off; off >>= 1) ssum += __shfl_xor_sync(0xffffffffu, ssum, off);
    if (lane < 16) out[(size_t)row * 16 + lane] = o - m - logf(ssum);
}

// ---------------------------------------------------------------------------
extern "C" void kernel_launch(void* const* d_in, const int* in_sizes, int n_in,
                              void* d_out, int out_size) {
    const float* x   = (const float*)d_in[0];
    const int*   src = (const int*)  d_in[1];
    const int*   dst = (const int*)  d_in[2];
    const float* av  = (const float*)d_in[3];
    const float* W1  = (const float*)d_in[4];
    const float* b1  = (const float*)d_in[5];
    const float* W2  = (const float*)d_in[6];
    const float* b2  = (const float*)d_in[7];
    const float* W3  = (const float*)d_in[8];
    const float* b3  = (const float*)d_in[9];
    const float* W4  = (const float*)d_in[10];
    const float* b4  = (const float*)d_in[11];
    const float* W5  = (const float*)d_in[12];
    const float* b5  = (const float*)d_in[13];
    float* out = (float*)d_out;

    // Dynamic smem sizes (bytes)
    const int SM_L1  = (NH * (NF + 4) + HL_NW * HL_TILE * NF + NH) * 4;  // 54528
    const int SM_L23 = (NH * (NH + 4) + HL_NW * HL_TILE * NH + NH) * 4;  // 27904
    // Unconditional every call: idempotent, capture-safe, no static guards.
    cudaFuncSetAttribute(k_hyplinear<NF, HL_TILE, HL_NW, false>,
                         cudaFuncAttributeMaxDynamicSharedMemorySize, SM_L1);

    int rowBlocks = (N_NODES + 7) / 8;          // 8 warps/block row kernels
    int hlBlocks = (N_NODES + HL_NW * HL_TILE - 1) / (HL_NW * HL_TILE);  // 2500

    k_bias<<<1, 96>>>(b1, b2, b3);
    k_init<<<rowBlocks, 256>>>(x);              // also zeroes d_cnt
    k_build<<<(E_EDGES + 255) / 256, 256>>>(src, dst, av);

    // Layer 1 (DIN=128)
    k_hyplinear<NF, HL_TILE, HL_NW, false><<<hlBlocks, HL_NW * 32, SM_L1>>>(d_h0, W1, 0);
    k_agg<<<rowBlocks, 256>>>();
    // Layer 2 (DIN=64, HypAct fused into staging)
    k_hyplinear<NH, HL_TILE, HL_NW, true><<<hlBlocks, HL_NW * 32, SM_L23>>>(nullptr, W2, 1);
    k_agg<<<rowBlocks, 256>>>();
    // Layer 3 (DIN=64, HypAct fused)
    k_hyplinear<NH, HL_TILE, HL_NW, true><<<hlBlocks, HL_NW * 32, SM_L23>>>(nullptr, W3, 2);
    k_agg<<<rowBlocks, 256>>>();

    // Head (final HypAct fused): 32 warps/block.
    int headBlocks = (N_NODES + 31) / 32;
    k_head<<<headBlocks, 1024>>>(W4, b4, W5, b5, out);
}